// round 5
// baseline (speedup 1.0000x reference)
#include <cuda_runtime.h>
#include <stdint.h>

// MessagePassing: out[dst[e]] += x[src[e]], N=100000, E=1600000, D=32 fp32.
// edge_index int32 [2, E]: row 0 = src, row 1 = dst.
//
// Structural rewrite: single-pass binning (counting sort by dst, fixed
// capacity, no prefix scan) converts 205MB of RED atomic L2 traffic into
// register accumulation + one 128B store per node.
//   A) zero out + counts
//   B) per edge: p = atomicAdd(counts[d]); bins[d*64+p] = s (RED fallback on
//      overflow -> unconditional correctness)
//   C) per node (8 lanes): gather <=64 rows, accumulate in regs, store once.

#define D_FEAT    32
#define CHUNKS    8        // D_FEAT / 4
#define MAX_NODES 100000
#define BIN_CAP   64       // Poisson(16) degree; P(>64) ~ 0, RED fallback covers it

__device__ int g_counts[MAX_NODES];
__device__ int g_bins[(long)MAX_NODES * BIN_CAP];

__device__ __forceinline__ void red_add_v4(float* p, float4 v) {
    asm volatile("red.global.add.v4.f32 [%0], {%1, %2, %3, %4};"
                 :: "l"(p), "f"(v.x), "f"(v.y), "f"(v.z), "f"(v.w)
                 : "memory");
}

// Phase A: zero out (n4 float4s) and counts (n_nodes ints).
__global__ void mp_zero_kernel(float4* __restrict__ out, long n4, int n_nodes) {
    long i = (long)blockIdx.x * blockDim.x + threadIdx.x;
    if (i < n4) out[i] = make_float4(0.f, 0.f, 0.f, 0.f);
    if (i < n_nodes) g_counts[i] = 0;
}

// Phase B: bin edges by dst.
__global__ void mp_bin_kernel(const float4* __restrict__ x,
                              const int* __restrict__ src,
                              const int* __restrict__ dst,
                              float* __restrict__ out,
                              long n_edges) {
    long e = (long)blockIdx.x * blockDim.x + threadIdx.x;
    if (e >= n_edges) return;
    int s = __ldg(&src[e]);
    int d = __ldg(&dst[e]);
    int p = atomicAdd(&g_counts[d], 1);
    if (p < BIN_CAP) {
        g_bins[(long)d * BIN_CAP + p] = s;
    } else {
        // Overflow fallback (statistically never taken): direct RED.
        #pragma unroll
        for (int c = 0; c < CHUNKS; ++c) {
            float4 v = __ldg(&x[(long)s * CHUNKS + c]);
            red_add_v4(out + (long)d * D_FEAT + c * 4, v);
        }
    }
}

// Phase C: per-node gather + register accumulate + single store.
// 8 lanes per node; lane c owns 16B chunk c of the feature row.
__global__ void mp_gather_kernel(const float4* __restrict__ x,
                                 float4* __restrict__ out,
                                 int n_nodes) {
    long t = (long)blockIdx.x * blockDim.x + threadIdx.x;
    int n = (int)(t >> 3);
    int c = (int)(t & 7);
    if (n >= n_nodes) return;

    int k = g_counts[n];
    if (k > BIN_CAP) k = BIN_CAP;

    long op = (long)n * CHUNKS + c;
    float4 acc = out[op];   // seeds with RED-fallback contributions (normally 0)

    const int4* bp = (const int4*)(g_bins + (long)n * BIN_CAP);
    int nf = k >> 2;
    for (int j = 0; j < nf; ++j) {
        int4 s = __ldg(&bp[j]);
        // 4 independent gathers (MLP=4) before the dependent adds.
        float4 a0 = __ldg(&x[(long)s.x * CHUNKS + c]);
        float4 a1 = __ldg(&x[(long)s.y * CHUNKS + c]);
        float4 a2 = __ldg(&x[(long)s.z * CHUNKS + c]);
        float4 a3 = __ldg(&x[(long)s.w * CHUNKS + c]);
        acc.x += a0.x; acc.y += a0.y; acc.z += a0.z; acc.w += a0.w;
        acc.x += a1.x; acc.y += a1.y; acc.z += a1.z; acc.w += a1.w;
        acc.x += a2.x; acc.y += a2.y; acc.z += a2.z; acc.w += a2.w;
        acc.x += a3.x; acc.y += a3.y; acc.z += a3.z; acc.w += a3.w;
    }
    for (int i = nf << 2; i < k; ++i) {
        int s = __ldg(&g_bins[(long)n * BIN_CAP + i]);
        float4 a = __ldg(&x[(long)s * CHUNKS + c]);
        acc.x += a.x; acc.y += a.y; acc.z += a.z; acc.w += a.w;
    }
    out[op] = acc;
}

// Safety path (shape mismatch): R4 edge-centric RED kernel.
__global__ void mp_scatter_kernel(const float4* __restrict__ x,
                                  const int* __restrict__ src,
                                  const int* __restrict__ dst,
                                  float* __restrict__ out,
                                  long n_edges) {
    long t = (long)blockIdx.x * blockDim.x + threadIdx.x;
    long e = t >> 3;
    int  c = (int)(t & 7);
    if (e >= n_edges) return;
    int s = __ldg(&src[e]);
    int d = __ldg(&dst[e]);
    float4 v = __ldg(&x[(long)s * CHUNKS + c]);
    red_add_v4(out + (long)d * D_FEAT + c * 4, v);
}

extern "C" void kernel_launch(void* const* d_in, const int* in_sizes, int n_in,
                              void* d_out, int out_size) {
    const float4* x   = (const float4*)d_in[0];
    const int*    ei  = (const int*)d_in[1];
    long n_edges = (long)in_sizes[1] / 2;
    const int* src = ei;
    const int* dst = ei + n_edges;
    float* out = (float*)d_out;
    int n_nodes = in_sizes[0] / D_FEAT;

    long n4 = (long)out_size / 4;
    int threads = 256;

    if (n_nodes > MAX_NODES) {
        // Shape-safety fallback: edge-centric RED path.
        long zb = (n4 + threads - 1) / threads;
        mp_zero_kernel<<<(unsigned)zb, threads>>>((float4*)out, n4, 0);
        long total = n_edges * CHUNKS;
        long blocks = (total + threads - 1) / threads;
        mp_scatter_kernel<<<(unsigned)blocks, threads>>>(x, src, dst, out, n_edges);
        return;
    }

    // Phase A: zero out + counts.
    {
        long mx = n4 > n_nodes ? n4 : n_nodes;
        long blocks = (mx + threads - 1) / threads;
        mp_zero_kernel<<<(unsigned)blocks, threads>>>((float4*)out, n4, n_nodes);
    }
    // Phase B: bin edges by dst.
    {
        long blocks = (n_edges + threads - 1) / threads;
        mp_bin_kernel<<<(unsigned)blocks, threads>>>(x, src, dst, out, n_edges);
    }
    // Phase C: per-node gather-accumulate.
    {
        long total = (long)n_nodes * 8;
        long blocks = (total + threads - 1) / threads;
        mp_gather_kernel<<<(unsigned)blocks, threads>>>(x, (float4*)out, n_nodes);
    }
}